// round 17
// baseline (speedup 1.0000x reference)
#include <cuda_runtime.h>
#include <cuda_fp16.h>

#define BB   256
#define TT   512
#define HH   128
#define G4   512
#define IND  10
#define RPC  8          // batch rows per CTA
#define HPAD 168        // halves per hbuf row
#define XGP  516        // padded floats per xg smem row (bank-conflict-free)

// ---------------- helpers ----------------
__device__ __forceinline__ float tanhapx(float x) {
    float y; asm("tanh.approx.f32 %0, %1;" : "=f"(y) : "f"(x)); return y;
}
__device__ __forceinline__ float sigapx(float x) {
    return fmaf(0.5f, tanhapx(0.5f * x), 0.5f);
}

// ---------------- device-global scratch ----------------
__device__ __half g_wA0[G4 * 144];               // [512][144] = [w_hh0 | w_ih0 pad16]
__device__ __half g_wA1[G4 * 128];               // [512][128] = w_hh1
__device__ __half g_wih1r[G4 * HH];              // w_ih1 row-major (xgate)
__device__ __half g_h1h[(size_t)BB * TT * HH];   // layer0 hidden, fp16
// xg layout: [bb][t][b][g]  row = ((batch>>3)*512 + t)*8 + (batch&7), 512 floats/row
__device__ float  g_xg1[(size_t)BB * TT * G4];
__device__ float  g_h2last[BB * HH];

__global__ void prep_kernel(const float* __restrict__ w_hh0,
                            const float* __restrict__ w_ih0,
                            const float* __restrict__ w_hh1,
                            const float* __restrict__ w_ih1)
{
    int idx = blockIdx.x * blockDim.x + threadIdx.x;   // 204800 threads
    if (idx < 73728) {                                  // g_wA0 [512][144]
        int g = idx / 144, k = idx - g * 144;
        float v = 0.0f;
        if (k < 128)       v = w_hh0[g * 128 + k];
        else if (k < 138)  v = w_ih0[g * 10 + (k - 128)];
        g_wA0[idx] = __float2half(v);
    } else if (idx < 139264) {                          // g_wA1 [512][128]
        int e = idx - 73728;
        g_wA1[e] = __float2half(w_hh1[e]);
    } else if (idx < 204800) {                          // g_wih1r
        int e = idx - 139264;
        g_wih1r[e] = __float2half(w_ih1[e]);
    }
}

// ---------------- LSTM recurrence on tensor cores ----------------
// 32 CTAs x 8 batch rows, 256 threads (8 warps).
// gates[512, 8] = A(W)[512, K] @ B(h^T)[K, 8];  K = 144 (L0: h|x) / 128 (L1).
// Warp w owns M-tiles {w, w+8, w+16, w+24} -> all 4 gates of units
// 16w+grp, 16w+grp+8 in the SAME thread. A frags in registers.
// R17: B-frag LDS hoisted out of the mma loop; each tile accumulates in TWO
// chains (even/odd k-blocks) -> mma dependency depth 8 -> 4.
template<int LAYER>
__global__ void __launch_bounds__(256, 1) lstm_mma_kernel(
    const float* __restrict__ x,
    const float* __restrict__ b_ih,
    const float* __restrict__ b_hh)
{
    constexpr int K    = (LAYER == 0) ? 144 : 128;
    constexpr int KBLK = K / 16;
    __shared__ __align__(16) __half hbuf[2][RPC][HPAD];
    __shared__ __align__(16) float  xgsm[2][RPC * XGP];   // used by LAYER==1 only

    const int tid  = threadIdx.x;
    const int bb   = blockIdx.x;
    const int warp = tid >> 5, lane = tid & 31;
    const int grp  = lane >> 2, tig = lane & 3;

    // zero both h buffers (h[-1] = 0, x pad = 0)
    for (int i = tid; i < 2 * RPC * HPAD; i += 256)
        ((__half*)hbuf)[i] = __float2half(0.0f);
    __syncthreads();                       // zero-fill visible before x[0] write

    // A fragments (weights) into registers — loop-invariant
    unsigned a[4][KBLK][4];
    const __half* Ag = (LAYER == 0) ? g_wA0 : g_wA1;
    #pragma unroll
    for (int tile = 0; tile < 4; tile++) {
        int mt = warp + tile * 8;
        int r0 = mt * 16 + grp, r1 = r0 + 8;
        #pragma unroll
        for (int kk = 0; kk < KBLK; kk++) {
            int c0 = kk * 16 + tig * 2;
            a[tile][kk][0] = *(const unsigned*)(Ag + r0 * K + c0);
            a[tile][kk][1] = *(const unsigned*)(Ag + r1 * K + c0);
            a[tile][kk][2] = *(const unsigned*)(Ag + r0 * K + c0 + 8);
            a[tile][kk][3] = *(const unsigned*)(Ag + r1 * K + c0 + 8);
        }
    }

    // bias — LAYER 0 only (layer1 bias already folded into g_xg1)
    float bias[4][2];
    if (LAYER == 0) {
        #pragma unroll
        for (int tile = 0; tile < 4; tile++) {
            int g0 = (warp + tile * 8) * 16 + grp;
            bias[tile][0] = b_ih[g0]     + b_hh[g0];
            bias[tile][1] = b_ih[g0 + 8] + b_hh[g0 + 8];
        }
    }

    const int u1 = 16 * warp + grp;             // thread's units: u1, u1+8
    const int bA = 2 * tig, bB = 2 * tig + 1;   // thread's batch cols

    float cst[4] = {0.f, 0.f, 0.f, 0.f};

    // layer0: x[0] into hbuf[0] k-columns 128..137
    int xb = 0, xj = 0;
    if (LAYER == 0) {
        if (tid < RPC * IND) {
            xb = tid / IND; xj = tid - xb * IND;
            hbuf[0][xb][128 + xj] =
                __float2half(x[((size_t)(RPC * bb + xb) * TT + 0) * IND + xj]);
        }
    }
    // layer1: stage xg block for t=0 into xgsm[0] (coalesced)
    if (LAYER == 1) {
        const uint4* src = (const uint4*)(g_xg1 + (size_t)bb * 512 * 4096);
        #pragma unroll
        for (int i = 0; i < 4; i++) {
            uint4 v = src[i * 256 + tid];
            int o = (i * 256 + tid) * 4;
            int b = o >> 9, g = o & 511;
            *(uint4*)&xgsm[0][b * XGP + g] = v;
        }
    }
    __syncthreads();

    for (int t = 0; t < TT; t++) {
        const int cur = t & 1, nxt = cur ^ 1;

        // [A] prefetch next step's inputs (latency hidden behind mma)
        float nx = 0.0f;
        uint4 ld[4];
        if (LAYER == 0) {
            if (tid < RPC * IND && t + 1 < TT)
                nx = x[((size_t)(RPC * bb + xb) * TT + (t + 1)) * IND + xj];
        } else {
            if (t + 1 < TT) {
                const uint4* src = (const uint4*)(g_xg1 +
                    ((size_t)bb * 512 + (t + 1)) * 4096);
                #pragma unroll
                for (int i = 0; i < 4; i++) ld[i] = src[i * 256 + tid];
            }
        }

        // [B0] hoist ALL B-fragment LDS (latency overlaps across k-blocks)
        unsigned bf[KBLK][2];
        #pragma unroll
        for (int kk = 0; kk < KBLK; kk++) {
            const __half* bp = &hbuf[cur][grp][kk * 16 + tig * 2];
            bf[kk][0] = *(const unsigned*)bp;
            bf[kk][1] = *(const unsigned*)(bp + 8);
        }

        // [B] acc init — L0: bias; L1: xg from smem (zero-conflict pattern)
        float acc[4][4], acc2[4][4];
        #pragma unroll
        for (int tile = 0; tile < 4; tile++) {
            if (LAYER == 0) {
                acc[tile][0] = bias[tile][0]; acc[tile][1] = bias[tile][0];
                acc[tile][2] = bias[tile][1]; acc[tile][3] = bias[tile][1];
            } else {
                int g0 = (warp + tile * 8) * 16 + grp;
                acc[tile][0] = xgsm[cur][bA * XGP + g0];
                acc[tile][1] = xgsm[cur][bB * XGP + g0];
                acc[tile][2] = xgsm[cur][bA * XGP + g0 + 8];
                acc[tile][3] = xgsm[cur][bB * XGP + g0 + 8];
            }
            acc2[tile][0] = 0.f; acc2[tile][1] = 0.f;
            acc2[tile][2] = 0.f; acc2[tile][3] = 0.f;
        }

        // [C] mma over K: dual accumulator chains per tile (depth 8 -> 4)
        #pragma unroll
        for (int kk = 0; kk < KBLK; kk++) {
            #pragma unroll
            for (int tile = 0; tile < 4; tile++) {
                float* dst = (kk & 1) ? acc2[tile] : acc[tile];
                asm volatile(
                    "mma.sync.aligned.m16n8k16.row.col.f32.f16.f16.f32 "
                    "{%0,%1,%2,%3}, {%4,%5,%6,%7}, {%8,%9}, {%0,%1,%2,%3};"
                    : "+f"(dst[0]), "+f"(dst[1]), "+f"(dst[2]), "+f"(dst[3])
                    : "r"(a[tile][kk][0]), "r"(a[tile][kk][1]),
                      "r"(a[tile][kk][2]), "r"(a[tile][kk][3]),
                      "r"(bf[kk][0]), "r"(bf[kk][1]));
            }
        }
        #pragma unroll
        for (int tile = 0; tile < 4; tile++) {
            acc[tile][0] += acc2[tile][0];
            acc[tile][1] += acc2[tile][1];
            acc[tile][2] += acc2[tile][2];
            acc[tile][3] += acc2[tile][3];
        }

        // [D] activations — all 4 gates of each cell live in THIS thread
        float hn[4];
        #pragma unroll
        for (int cell = 0; cell < 4; cell++) {
            float gi = acc[0][cell], gf = acc[1][cell];
            float gg = acc[2][cell], go = acc[3][cell];
            cst[cell] = sigapx(gf) * cst[cell] + sigapx(gi) * tanhapx(gg);
            hn[cell]  = sigapx(go) * tanhapx(cst[cell]);
        }
        hbuf[nxt][bA][u1]     = __float2half(hn[0]);
        hbuf[nxt][bB][u1]     = __float2half(hn[1]);
        hbuf[nxt][bA][u1 + 8] = __float2half(hn[2]);
        hbuf[nxt][bB][u1 + 8] = __float2half(hn[3]);

        if (LAYER == 0) {
            if (tid < RPC * IND) hbuf[nxt][xb][128 + xj] = __float2half(nx);
        } else {
            if (t + 1 < TT) {
                #pragma unroll
                for (int i = 0; i < 4; i++) {
                    int o = (i * 256 + tid) * 4;
                    int b = o >> 9, g = o & 511;
                    *(uint4*)&xgsm[nxt][b * XGP + g] = ld[i];
                }
            }
        }
        __syncthreads();

        if (LAYER == 0) {
            // export h[t] coalesced: warp = batch row, lane covers 4 units
            uint2 v = *(const uint2*)&hbuf[nxt][warp][lane * 4];
            *(uint2*)&g_h1h[((size_t)(RPC * bb + warp) * TT + t) * HH + lane * 4] = v;
        } else if (t == TT - 1) {
            g_h2last[(RPC * bb + bA) * HH + u1]     = hn[0];
            g_h2last[(RPC * bb + bB) * HH + u1]     = hn[1];
            g_h2last[(RPC * bb + bA) * HH + u1 + 8] = hn[2];
            g_h2last[(RPC * bb + bB) * HH + u1 + 8] = hn[3];
        }
    }
}

// ---------------- xgate via tensor cores (R16 version, unchanged) ----------------
#define XG_PAD 136
#define XG_SMEM (2 * 128 * XG_PAD * 2 + 512)

__global__ void __launch_bounds__(256) xgate_mma_kernel(
    const float* __restrict__ b_ih1, const float* __restrict__ b_hh1)
{
    extern __shared__ char smem[];
    __half* As   = (__half*)smem;
    __half* Bs   = (__half*)(smem + 128 * XG_PAD * 2);
    float*  bias = (float*)(smem + 2 * 128 * XG_PAD * 2);

    const int tid = threadIdx.x;
    const int m0  = blockIdx.x * 128;
    const int n0  = blockIdx.y * 128;

    {
        const uint4* src = (const uint4*)(g_h1h + (size_t)m0 * HH);
        const uint4* wsr = (const uint4*)(g_wih1r + (size_t)n0 * HH);
        #pragma unroll
        for (int i = 0; i < 8; i++) {
            int idx = i * 256 + tid;
            int row = idx >> 4;
            int kc  = (idx & 15) << 3;
            *(uint4*)(As + row * XG_PAD + kc) = src[idx];
            *(uint4*)(Bs + row * XG_PAD + kc) = wsr[idx];
        }
        if (tid < 128) bias[tid] = b_ih1[n0 + tid] + b_hh1[n0 + tid];
    }
    __syncthreads();

    const int warp = tid >> 5, lane = tid & 31;
    const int grp  = lane >> 2, tig = lane & 3;
    const int arow = warp * 16 + grp;

    unsigned int a[8][4];
    #pragma unroll
    for (int kk = 0; kk < 8; kk++) {
        const __half* base = As + arow * XG_PAD + kk * 16 + tig * 2;
        a[kk][0] = *(const unsigned int*)(base);
        a[kk][1] = *(const unsigned int*)(base + 8 * XG_PAD);
        a[kk][2] = *(const unsigned int*)(base + 8);
        a[kk][3] = *(const unsigned int*)(base + 8 * XG_PAD + 8);
    }

    // output row remap: m = batch*512 + t  ->  row = ((batch>>3)*512 + t)*8 + (batch&7)
    const int mA    = m0 + arow;
    const int batch = mA >> 9, tA = mA & 511;
    const size_t rowA = ((size_t)(batch >> 3) * 512 + tA) * 8 + (batch & 7);
    const size_t rowB = rowA + 64;         // m+8 -> t+8 (same batch) -> +8*8 rows

    #pragma unroll
    for (int j = 0; j < 16; j++) {
        float c0 = 0.f, c1 = 0.f, c2 = 0.f, c3 = 0.f;
        const __half* bbase = Bs + (j * 8 + grp) * XG_PAD + tig * 2;
        #pragma unroll
        for (int kk = 0; kk < 8; kk++) {
            unsigned int b0 = *(const unsigned int*)(bbase + kk * 16);
            unsigned int b1 = *(const unsigned int*)(bbase + kk * 16 + 8);
            asm volatile(
                "mma.sync.aligned.m16n8k16.row.col.f32.f16.f16.f32 "
                "{%0,%1,%2,%3}, {%4,%5,%6,%7}, {%8,%9}, {%0,%1,%2,%3};"
                : "+f"(c0), "+f"(c1), "+f"(c2), "+f"(c3)
                : "r"(a[kk][0]), "r"(a[kk][1]), "r"(a[kk][2]), "r"(a[kk][3]),
                  "r"(b0), "r"(b1));
        }
        int col = j * 8 + tig * 2;
        float bv0 = bias[col], bv1 = bias[col + 1];
        float2* o0 = (float2*)(g_xg1 + rowA * G4 + n0 + col);
        float2* o1 = (float2*)(g_xg1 + rowB * G4 + n0 + col);
        *o0 = make_float2(c0 + bv0, c1 + bv1);
        *o1 = make_float2(c2 + bv0, c3 + bv1);
    }
}

// ---------------- final FC (warp per batch row) ----------------
__global__ void fc_kernel(const float* __restrict__ fc_w,
                          const float* __restrict__ fc_b,
                          float* __restrict__ out)
{
    int b    = blockIdx.x * 8 + (threadIdx.x >> 5);
    int lane = threadIdx.x & 31;
    float4 h = *(const float4*)(g_h2last + b * HH + lane * 4);
    #pragma unroll
    for (int c = 0; c < 10; c++) {
        float4 w = *(const float4*)(fc_w + c * HH + lane * 4);
        float p = h.x * w.x + h.y * w.y + h.z * w.z + h.w * w.w;
        #pragma unroll
        for (int s = 16; s > 0; s >>= 1)
            p += __shfl_xor_sync(0xffffffffu, p, s);
        if (lane == 0) out[b * 10 + c] = p + fc_b[c];
    }
}

extern "C" void kernel_launch(void* const* d_in, const int* in_sizes, int n_in,
                              void* d_out, int out_size)
{
    const float* x     = (const float*)d_in[0];
    const float* w_ih0 = (const float*)d_in[1];
    const float* w_hh0 = (const float*)d_in[2];
    const float* b_ih0 = (const float*)d_in[3];
    const float* b_hh0 = (const float*)d_in[4];
    const float* w_ih1 = (const float*)d_in[5];
    const float* w_hh1 = (const float*)d_in[6];
    const float* b_ih1 = (const float*)d_in[7];
    const float* b_hh1 = (const float*)d_in[8];
    const float* fc_w  = (const float*)d_in[9];
    const float* fc_b  = (const float*)d_in[10];
    float* out = (float*)d_out;

    cudaFuncSetAttribute(xgate_mma_kernel,
                         cudaFuncAttributeMaxDynamicSharedMemorySize, XG_SMEM);

    prep_kernel<<<800, 256>>>(w_hh0, w_ih0, w_hh1, w_ih1);
    lstm_mma_kernel<0><<<BB / RPC, 256>>>(x, b_ih0, b_hh0);
    {
        dim3 grid(BB * TT / 128, G4 / 128);
        xgate_mma_kernel<<<grid, 256, XG_SMEM>>>(b_ih1, b_hh1);
    }
    lstm_mma_kernel<1><<<BB / RPC, 256>>>(nullptr, b_ih1, b_hh1);
    fc_kernel<<<32, 256>>>(fc_w, fc_b, out);
}